// round 8
// baseline (speedup 1.0000x reference)
#include <cuda_runtime.h>
#include <cstdint>

#define N 384
#define C 64
#define W_COLS 512
#define TMAIN 512
#define NI 64             // i-rows per CTA
#define KCH 48            // k-chunk per stage
#define NCHUNK (N / KCH)  // 8
#define AS_LD 388         // fp32 words per B row (conflict-free fragment LDS)
#define Q_LD 68           // QT smem row stride (conflict-free fold)
#define NBUF 2
#define NWARP 16

// ---------------- scratch ----------------
__device__ float g_W[N * W_COLS];        // x @ w_w^T  [384][512]
__device__ float g_P[N * N];             // exp(AB)  [i][j]
__device__ float g_QT[N * N];            // exp(CD) transposed: QT[k][i]
__device__ float g_RT[N * N];            // exp(EF) transposed, tf32-rounded: RT[k][j]
__device__ float g_num[N * C];
__device__ float g_den[N];
__device__ unsigned g_ctr = 0;           // last-CTA-finishes counter (self-resetting)

__device__ __forceinline__ float to_tf32(float x) {
    float r;
    asm("cvt.rna.tf32.f32 %0, %1;" : "=f"(r) : "f"(x));
    return r;
}
__device__ __forceinline__ void cp16(uint32_t dst, const void* src) {
    asm volatile("cp.async.cg.shared.global [%0], [%1], 16;" :: "r"(dst), "l"(src));
}

// ---------------- K1: W = x @ w_w^T ----------------
__global__ void k_gemm_w(const float* __restrict__ x, const float* __restrict__ ww) {
    int idx = blockIdx.x * blockDim.x + threadIdx.x;
    if (idx >= N * W_COLS) return;
    int n = idx / W_COLS;
    int o = idx - n * W_COLS;
    const float4* xr = (const float4*)(x + n * C);
    const float4* wr = (const float4*)(ww + o * C);
    float s = 0.f;
#pragma unroll
    for (int c = 0; c < C / 4; ++c) {
        float4 a = xr[c], b = wr[c];
        s += a.x * b.x + a.y * b.y + a.z * b.z + a.w * b.w;
    }
    g_W[idx] = s;
}

// ---------------- K2: fused scores + exp (+transposes), 32x32 tiles ----------------
// No max-shift: scores are O(1) (w scaled 0.05); any per-matrix shift cancels in num/den.
__global__ void k_pqr() {
    __shared__ float us[32][67], vs[32][67];
    int z = blockIdx.z;
    int r0 = blockIdx.y * 32, c0 = blockIdx.x * 32;
    int tx = threadIdx.x, ty = threadIdx.y;
    int t = ty * 16 + tx;
    int up = (z == 0) ? 0 : (z == 1) ? 3 : 5;
    int vp = (z == 0) ? 1 : (z == 1) ? 2 : 4;
    for (int q = t; q < 32 * 64; q += 256) {
        int rr = q >> 6, cc = q & 63;
        us[rr][cc] = g_W[(r0 + rr) * W_COLS + up * C + cc];
        vs[rr][cc] = g_W[(c0 + rr) * W_COLS + vp * C + cc];
    }
    __syncthreads();
    float s00 = 0.f, s01 = 0.f, s10 = 0.f, s11 = 0.f;
#pragma unroll
    for (int c = 0; c < 64; ++c) {
        float u0 = us[2 * ty][c], u1 = us[2 * ty + 1][c];
        float v0 = vs[2 * tx][c], v1 = vs[2 * tx + 1][c];
        s00 += u0 * v0; s01 += u0 * v1;
        s10 += u1 * v0; s11 += u1 * v1;
    }
    s00 = __expf(s00 * 0.125f);
    s01 = __expf(s01 * 0.125f);
    s10 = __expf(s10 * 0.125f);
    s11 = __expf(s11 * 0.125f);
    int row = r0 + 2 * ty, col = c0 + 2 * tx;
    if (z == 0) {
        g_P[row * N + col] = s00;       g_P[row * N + col + 1] = s01;
        g_P[(row + 1) * N + col] = s10; g_P[(row + 1) * N + col + 1] = s11;
    } else if (z == 1) {
        g_QT[row * N + col] = s00;       g_QT[row * N + col + 1] = s01;
        g_QT[(row + 1) * N + col] = s10; g_QT[(row + 1) * N + col + 1] = s11;
    } else {
        g_RT[row * N + col] = to_tf32(s00);       g_RT[row * N + col + 1] = to_tf32(s01);
        g_RT[(row + 1) * N + col] = to_tf32(s10); g_RT[(row + 1) * N + col + 1] = to_tf32(s11);
    }
}

// ---------------- K3: tf32 HMMA main contraction + fused finalize ----------------
// grid = (65, 6): blockIdx.x = d (64 => denominator), blockIdx.y = i-tile (64 rows)
#define B_BYTES (KCH * AS_LD * 4)                  // 74496
#define Q_BYTES (KCH * Q_LD * 4)                   // 13056
#define OFF_B   0
#define OFF_QT  (NBUF * B_BYTES)                   // 148992
#define OFF_V1  (OFF_QT + NBUF * Q_BYTES)          // 175104
#define OFF_V2  (OFF_V1 + N * 4)
#define OFF_PP  (OFF_V2 + N * 4)
#define SMEM_BYTES (OFF_PP + NWARP * NI * 4)       // 182272

__device__ __forceinline__ void mma_tf32(float* c, const uint32_t* a, const uint32_t* b) {
    asm("mma.sync.aligned.m16n8k8.row.col.f32.tf32.tf32.f32 "
        "{%0,%1,%2,%3}, {%4,%5,%6,%7}, {%8,%9}, {%0,%1,%2,%3};"
        : "+f"(c[0]), "+f"(c[1]), "+f"(c[2]), "+f"(c[3])
        : "r"(a[0]), "r"(a[1]), "r"(a[2]), "r"(a[3]), "r"(b[0]), "r"(b[1]));
}

__global__ __launch_bounds__(TMAIN, 1) void k_main(float* __restrict__ out) {
    extern __shared__ char smc[];
    float* v1s = (float*)(smc + OFF_V1);
    float* v2s = (float*)(smc + OFF_V2);
    float* pp  = (float*)(smc + OFF_PP);

    int d = blockIdx.x;
    int i0 = blockIdx.y * NI;
    int t = threadIdx.x;
    int w = t >> 5, lane = t & 31;
    int g = lane >> 2, tg = lane & 3;
    int j0w = w * 24;                 // 16 warps x 24 j-cols

    uint32_t smb = (uint32_t)__cvta_generic_to_shared(smc);

    // Stage chunk 0 into buffer 0
    {
        for (int q = t; q < KCH * (N / 4); q += TMAIN) {
            int r = q / (N / 4), u = q - r * (N / 4);
            cp16(smb + OFF_B + (uint32_t)(r * AS_LD + u * 4) * 4u, &g_RT[r * N + u * 4]);
        }
        for (int q = t; q < KCH * (NI / 4); q += TMAIN) {
            int r = q / (NI / 4), u = q - r * (NI / 4);
            cp16(smb + OFF_QT + (uint32_t)(r * Q_LD + u * 4) * 4u, &g_QT[r * N + i0 + u * 4]);
        }
        asm volatile("cp.async.commit_group;" ::: "memory");
    }

    if (d < C) {
        for (int j = t; j < N; j += TMAIN) {
            v1s[j] = g_W[j * W_COLS + 6 * C + d];
            v2s[j] = g_W[j * W_COLS + 7 * C + d];
        }
    } else {
        for (int j = t; j < N; j += TMAIN) { v1s[j] = 1.f; v2s[j] = 1.f; }
    }
    __syncthreads();

    // Hoist A fragments into registers: chunk-invariant, built from g_P * v1
    uint32_t a[4][3][4];
#pragma unroll
    for (int mt = 0; mt < 4; ++mt)
#pragma unroll
        for (int js = 0; js < 3; ++js) {
            int i = i0 + mt * 16 + g;
            int j = j0w + js * 8 + tg;
            float v1a = v1s[j], v1b = v1s[j + 4];
            a[mt][js][0] = __float_as_uint(to_tf32(g_P[i * N + j] * v1a));
            a[mt][js][1] = __float_as_uint(to_tf32(g_P[(i + 8) * N + j] * v1a));
            a[mt][js][2] = __float_as_uint(to_tf32(g_P[i * N + j + 4] * v1b));
            a[mt][js][3] = __float_as_uint(to_tf32(g_P[(i + 8) * N + j + 4] * v1b));
        }

    float numacc[8];
#pragma unroll
    for (int s = 0; s < 8; ++s) numacc[s] = 0.f;

    for (int ch = 0; ch < NCHUNK; ++ch) {
        if (ch + 1 < NCHUNK) {
            uint32_t bo = OFF_B + (uint32_t)((ch + 1) & 1) * B_BYTES;
            uint32_t qo = OFF_QT + (uint32_t)((ch + 1) & 1) * Q_BYTES;
            int k0 = (ch + 1) * KCH;
            for (int q = t; q < KCH * (N / 4); q += TMAIN) {
                int r = q / (N / 4), u = q - r * (N / 4);
                cp16(smb + bo + (uint32_t)(r * AS_LD + u * 4) * 4u, &g_RT[(k0 + r) * N + u * 4]);
            }
            for (int q = t; q < KCH * (NI / 4); q += TMAIN) {
                int r = q / (NI / 4), u = q - r * (NI / 4);
                cp16(smb + qo + (uint32_t)(r * Q_LD + u * 4) * 4u, &g_QT[(k0 + r) * N + i0 + u * 4]);
            }
            asm volatile("cp.async.commit_group;" ::: "memory");
            asm volatile("cp.async.wait_group 1;" ::: "memory");
        } else {
            asm volatile("cp.async.wait_group 0;" ::: "memory");
        }
        __syncthreads();

        const float* Bb = (const float*)(smc + OFF_B + (ch & 1) * B_BYTES);
        const float* Qb = (const float*)(smc + OFF_QT + (ch & 1) * Q_BYTES);

#pragma unroll
        for (int sub = 0; sub < 3; ++sub) {       // 16 k-cols per sub-tile
            float acc[4][2][4];
#pragma unroll
            for (int mt = 0; mt < 4; ++mt)
#pragma unroll
                for (int nt = 0; nt < 2; ++nt)
#pragma unroll
                    for (int r = 0; r < 4; ++r) acc[mt][nt][r] = 0.f;

#pragma unroll
            for (int js = 0; js < 3; ++js) {
                uint32_t b[2][2];
#pragma unroll
                for (int nt = 0; nt < 2; ++nt) {
                    const uint32_t* bp = (const uint32_t*)(
                        Bb + (sub * 16 + nt * 8 + g) * AS_LD + j0w + js * 8 + tg);
                    b[nt][0] = bp[0];
                    b[nt][1] = bp[4];
                }
#pragma unroll
                for (int mt = 0; mt < 4; ++mt)
#pragma unroll
                    for (int nt = 0; nt < 2; ++nt)
                        mma_tf32(acc[mt][nt], a[mt][js], b[nt]);
            }

            // Fold: numacc += G * QT[k][i] * v2[k]
#pragma unroll
            for (int nt = 0; nt < 2; ++nt) {
                int kk0 = sub * 16 + nt * 8 + 2 * tg;
                float v2a = v2s[ch * KCH + kk0];
                float v2b = v2s[ch * KCH + kk0 + 1];
#pragma unroll
                for (int mt = 0; mt < 4; ++mt)
#pragma unroll
                    for (int r = 0; r < 4; ++r) {
                        int kk = kk0 + (r & 1);
                        int iloc = mt * 16 + ((r >> 1) << 3) + g;
                        numacc[mt * 2 + (r >> 1)] +=
                            acc[mt][nt][r] * Qb[kk * Q_LD + iloc] * ((r & 1) ? v2b : v2a);
                    }
            }
        }
        __syncthreads();  // all warps done reading this buffer before it's re-staged
    }

    // Reduce over quad lanes (tg), then across 16 warps via smem
#pragma unroll
    for (int s = 0; s < 8; ++s) {
        float v = numacc[s];
        v += __shfl_xor_sync(0xffffffffu, v, 1);
        v += __shfl_xor_sync(0xffffffffu, v, 2);
        if (tg == 0) {
            int iloc = (s >> 1) * 16 + (s & 1) * 8 + g;
            pp[w * NI + iloc] = v;
        }
    }
    __syncthreads();
    if (t < NI) {
        float tot = 0.f;
#pragma unroll
        for (int q = 0; q < NWARP; ++q) tot += pp[q * NI + t];
        int gi = i0 + t;
        if (d < C) g_num[gi * C + d] = tot;
        else       g_den[gi] = tot;
    }

    // Fused finalize: last CTA computes out = num / den
    __threadfence();
    __syncthreads();
    __shared__ unsigned s_last;
    if (t == 0) s_last = atomicAdd(&g_ctr, 1u);
    __syncthreads();
    if (s_last == gridDim.x * gridDim.y - 1) {
        for (int idx = t; idx < N * C; idx += TMAIN)
            out[idx] = g_num[idx] / g_den[idx / C];
        if (t == 0) atomicExch(&g_ctr, 0u);   // reset for next graph replay
    }
}

// ---------------- launcher ----------------
extern "C" void kernel_launch(void* const* d_in, const int* in_sizes, int n_in,
                              void* d_out, int out_size) {
    const float* x  = (const float*)d_in[0];
    const float* ww = (const float*)d_in[1];
    if (n_in >= 2 && in_sizes[0] == 8 * C * C && in_sizes[1] == N * C) {
        const float* tmp = x; x = ww; ww = tmp;
    }
    float* out = (float*)d_out;

    cudaFuncSetAttribute(k_main, cudaFuncAttributeMaxDynamicSharedMemorySize, SMEM_BYTES);

    k_gemm_w<<<(N * W_COLS + 255) / 256, 256>>>(x, ww);
    dim3 g2(N / 32, N / 32, 3);
    k_pqr<<<g2, dim3(16, 16)>>>();
    dim3 g3(C + 1, N / NI);
    k_main<<<g3, TMAIN, SMEM_BYTES>>>(out);
}

// round 9
// speedup vs baseline: 1.0505x; 1.0505x over previous
#include <cuda_runtime.h>
#include <cstdint>

#define N 384
#define C 64
#define W_COLS 512
#define THREADS 256
#define NI 64             // i-rows per CTA
#define KCH 48            // k-chunk per stage
#define NCHUNK (N / KCH)  // 8
#define AS_LD 388         // fp32 words per B row (conflict-free fragment LDS)
#define Q_LD 68           // QT smem row stride (conflict-free fold)
#define NBUF 2

// ---------------- scratch ----------------
__device__ float g_W[N * W_COLS];        // x @ w_w^T  [384][512]
__device__ float g_P[N * N];             // exp(AB)  [i][j]
__device__ float g_QT[N * N];            // exp(CD) transposed: QT[k][i]
__device__ float g_RT[N * N];            // exp(EF) transposed, tf32-rounded: RT[k][j]
__device__ float g_num[N * C];
__device__ float g_den[N];
__device__ unsigned g_ctr = 0;           // last-CTA counter (self-resetting)

__device__ __forceinline__ float to_tf32(float x) {
    float r;
    asm("cvt.rna.tf32.f32 %0, %1;" : "=f"(r) : "f"(x));
    return r;
}
__device__ __forceinline__ void cp16(uint32_t dst, const void* src) {
    asm volatile("cp.async.cg.shared.global [%0], [%1], 16;" :: "r"(dst), "l"(src));
}

// ---------------- K1: W = x @ w_w^T, smem-tiled 32x32 ----------------
__global__ void k_gemm_w(const float* __restrict__ x, const float* __restrict__ ww) {
    __shared__ float xs[32][67], ws[32][67];
    int o0 = blockIdx.x * 32, n0 = blockIdx.y * 32;
    int tx = threadIdx.x, ty = threadIdx.y;
    int t = ty * 16 + tx;
    for (int q = t; q < 32 * 64; q += 256) {
        int rr = q >> 6, cc = q & 63;
        xs[rr][cc] = x[(n0 + rr) * C + cc];
        ws[rr][cc] = ww[(o0 + rr) * C + cc];
    }
    __syncthreads();
    float s00 = 0.f, s01 = 0.f, s10 = 0.f, s11 = 0.f;
#pragma unroll
    for (int c = 0; c < 64; ++c) {
        float u0 = xs[2 * ty][c], u1 = xs[2 * ty + 1][c];
        float v0 = ws[2 * tx][c], v1 = ws[2 * tx + 1][c];
        s00 += u0 * v0; s01 += u0 * v1;
        s10 += u1 * v0; s11 += u1 * v1;
    }
    int n = n0 + 2 * ty, o = o0 + 2 * tx;
    g_W[n * W_COLS + o] = s00;       g_W[n * W_COLS + o + 1] = s01;
    g_W[(n + 1) * W_COLS + o] = s10; g_W[(n + 1) * W_COLS + o + 1] = s11;
}

// ---------------- K2: fused scores + exp (+transposes), 32x32 tiles ----------------
// No max-shift: scores are O(1) (w scaled 0.05); any per-matrix shift cancels in num/den.
__global__ void k_pqr() {
    __shared__ float us[32][67], vs[32][67];
    int z = blockIdx.z;
    int r0 = blockIdx.y * 32, c0 = blockIdx.x * 32;
    int tx = threadIdx.x, ty = threadIdx.y;
    int t = ty * 16 + tx;
    int up = (z == 0) ? 0 : (z == 1) ? 3 : 5;
    int vp = (z == 0) ? 1 : (z == 1) ? 2 : 4;
    for (int q = t; q < 32 * 64; q += 256) {
        int rr = q >> 6, cc = q & 63;
        us[rr][cc] = g_W[(r0 + rr) * W_COLS + up * C + cc];
        vs[rr][cc] = g_W[(c0 + rr) * W_COLS + vp * C + cc];
    }
    __syncthreads();
    float s00 = 0.f, s01 = 0.f, s10 = 0.f, s11 = 0.f;
#pragma unroll
    for (int c = 0; c < 64; ++c) {
        float u0 = us[2 * ty][c], u1 = us[2 * ty + 1][c];
        float v0 = vs[2 * tx][c], v1 = vs[2 * tx + 1][c];
        s00 += u0 * v0; s01 += u0 * v1;
        s10 += u1 * v0; s11 += u1 * v1;
    }
    s00 = __expf(s00 * 0.125f);
    s01 = __expf(s01 * 0.125f);
    s10 = __expf(s10 * 0.125f);
    s11 = __expf(s11 * 0.125f);
    int row = r0 + 2 * ty, col = c0 + 2 * tx;
    if (z == 0) {
        g_P[row * N + col] = s00;       g_P[row * N + col + 1] = s01;
        g_P[(row + 1) * N + col] = s10; g_P[(row + 1) * N + col + 1] = s11;
    } else if (z == 1) {
        g_QT[row * N + col] = s00;       g_QT[row * N + col + 1] = s01;
        g_QT[(row + 1) * N + col] = s10; g_QT[(row + 1) * N + col + 1] = s11;
    } else {
        g_RT[row * N + col] = to_tf32(s00);       g_RT[row * N + col + 1] = to_tf32(s01);
        g_RT[(row + 1) * N + col] = to_tf32(s10); g_RT[(row + 1) * N + col + 1] = to_tf32(s11);
    }
}

// ---------------- K3: tf32 HMMA main contraction + fused finalize ----------------
// grid = (65, 6): blockIdx.x = d (64 => denominator), blockIdx.y = i-tile (64 rows)
#define B_BYTES (KCH * AS_LD * 4)                  // 74496
#define Q_BYTES (KCH * Q_LD * 4)                   // 13056
#define OFF_B   0
#define OFF_QT  (NBUF * B_BYTES)                   // 148992
#define OFF_V1  (OFF_QT + NBUF * Q_BYTES)          // 175104
#define OFF_V2  (OFF_V1 + N * 4)
#define OFF_PP  (OFF_V2 + N * 4)
#define SMEM_BYTES (OFF_PP + 8 * NI * 4)           // 180224

__device__ __forceinline__ void mma_tf32(float* c, const uint32_t* a, const uint32_t* b) {
    asm("mma.sync.aligned.m16n8k8.row.col.f32.tf32.tf32.f32 "
        "{%0,%1,%2,%3}, {%4,%5,%6,%7}, {%8,%9}, {%0,%1,%2,%3};"
        : "+f"(c[0]), "+f"(c[1]), "+f"(c[2]), "+f"(c[3])
        : "r"(a[0]), "r"(a[1]), "r"(a[2]), "r"(a[3]), "r"(b[0]), "r"(b[1]));
}

__global__ __launch_bounds__(THREADS, 1) void k_main(float* __restrict__ out) {
    extern __shared__ char smc[];
    float* v1s = (float*)(smc + OFF_V1);
    float* v2s = (float*)(smc + OFF_V2);
    float* pp  = (float*)(smc + OFF_PP);

    int d = blockIdx.x;
    int i0 = blockIdx.y * NI;
    int t = threadIdx.x;
    int w = t >> 5, lane = t & 31;
    int g = lane >> 2, tg = lane & 3;
    int j0w = w * 48;

    uint32_t smb = (uint32_t)__cvta_generic_to_shared(smc);

    // Stage chunk 0 into buffer 0
    {
        for (int q = t; q < KCH * (N / 4); q += THREADS) {
            int r = q / (N / 4), u = q - r * (N / 4);
            cp16(smb + OFF_B + (uint32_t)(r * AS_LD + u * 4) * 4u, &g_RT[r * N + u * 4]);
        }
        for (int q = t; q < KCH * (NI / 4); q += THREADS) {
            int r = q / (NI / 4), u = q - r * (NI / 4);
            cp16(smb + OFF_QT + (uint32_t)(r * Q_LD + u * 4) * 4u, &g_QT[r * N + i0 + u * 4]);
        }
        asm volatile("cp.async.commit_group;" ::: "memory");
    }

    if (d < C) {
        for (int j = t; j < N; j += THREADS) {
            v1s[j] = g_W[j * W_COLS + 6 * C + d];
            v2s[j] = g_W[j * W_COLS + 7 * C + d];
        }
    } else {
        for (int j = t; j < N; j += THREADS) { v1s[j] = 1.f; v2s[j] = 1.f; }
    }
    __syncthreads();

    // Hoist A fragments into registers: chunk-invariant, built from g_P * v1
    uint32_t a[4][6][4];
#pragma unroll
    for (int mt = 0; mt < 4; ++mt)
#pragma unroll
        for (int js = 0; js < 6; ++js) {
            int i = i0 + mt * 16 + g;
            int j = j0w + js * 8 + tg;
            float v1a = v1s[j], v1b = v1s[j + 4];
            a[mt][js][0] = __float_as_uint(to_tf32(g_P[i * N + j] * v1a));
            a[mt][js][1] = __float_as_uint(to_tf32(g_P[(i + 8) * N + j] * v1a));
            a[mt][js][2] = __float_as_uint(to_tf32(g_P[i * N + j + 4] * v1b));
            a[mt][js][3] = __float_as_uint(to_tf32(g_P[(i + 8) * N + j + 4] * v1b));
        }

    float numacc[8];
#pragma unroll
    for (int s = 0; s < 8; ++s) numacc[s] = 0.f;

    for (int ch = 0; ch < NCHUNK; ++ch) {
        if (ch + 1 < NCHUNK) {
            uint32_t bo = OFF_B + (uint32_t)((ch + 1) & 1) * B_BYTES;
            uint32_t qo = OFF_QT + (uint32_t)((ch + 1) & 1) * Q_BYTES;
            int k0 = (ch + 1) * KCH;
            for (int q = t; q < KCH * (N / 4); q += THREADS) {
                int r = q / (N / 4), u = q - r * (N / 4);
                cp16(smb + bo + (uint32_t)(r * AS_LD + u * 4) * 4u, &g_RT[(k0 + r) * N + u * 4]);
            }
            for (int q = t; q < KCH * (NI / 4); q += THREADS) {
                int r = q / (NI / 4), u = q - r * (NI / 4);
                cp16(smb + qo + (uint32_t)(r * Q_LD + u * 4) * 4u, &g_QT[(k0 + r) * N + i0 + u * 4]);
            }
            asm volatile("cp.async.commit_group;" ::: "memory");
            asm volatile("cp.async.wait_group 1;" ::: "memory");
        } else {
            asm volatile("cp.async.wait_group 0;" ::: "memory");
        }
        __syncthreads();

        const float* Bb = (const float*)(smc + OFF_B + (ch & 1) * B_BYTES);
        const float* Qb = (const float*)(smc + OFF_QT + (ch & 1) * Q_BYTES);

#pragma unroll
        for (int sub = 0; sub < 3; ++sub) {       // 16 k-cols per sub-tile
            float acc[4][2][4];
#pragma unroll
            for (int mt = 0; mt < 4; ++mt)
#pragma unroll
                for (int nt = 0; nt < 2; ++nt)
#pragma unroll
                    for (int r = 0; r < 4; ++r) acc[mt][nt][r] = 0.f;

            // Software-pipelined B fragments (one js ahead)
            uint32_t bc[2][2];
#pragma unroll
            for (int nt = 0; nt < 2; ++nt) {
                const uint32_t* bp =
                    (const uint32_t*)(Bb + (sub * 16 + nt * 8 + g) * AS_LD + j0w + tg);
                bc[nt][0] = bp[0];
                bc[nt][1] = bp[4];
            }
#pragma unroll
            for (int js = 0; js < 6; ++js) {
                uint32_t bn[2][2];
                if (js < 5) {
#pragma unroll
                    for (int nt = 0; nt < 2; ++nt) {
                        const uint32_t* bp = (const uint32_t*)(
                            Bb + (sub * 16 + nt * 8 + g) * AS_LD + j0w + (js + 1) * 8 + tg);
                        bn[nt][0] = bp[0];
                        bn[nt][1] = bp[4];
                    }
                }
#pragma unroll
                for (int mt = 0; mt < 4; ++mt)
#pragma unroll
                    for (int nt = 0; nt < 2; ++nt)
                        mma_tf32(acc[mt][nt], a[mt][js], bc[nt]);
                if (js < 5) {
#pragma unroll
                    for (int nt = 0; nt < 2; ++nt) {
                        bc[nt][0] = bn[nt][0];
                        bc[nt][1] = bn[nt][1];
                    }
                }
            }

            // Fold: numacc += G * QT[k][i] * v2[k]
#pragma unroll
            for (int nt = 0; nt < 2; ++nt) {
                int kk0 = sub * 16 + nt * 8 + 2 * tg;
                float v2a = v2s[ch * KCH + kk0];
                float v2b = v2s[ch * KCH + kk0 + 1];
#pragma unroll
                for (int mt = 0; mt < 4; ++mt)
#pragma unroll
                    for (int r = 0; r < 4; ++r) {
                        int kk = kk0 + (r & 1);
                        int iloc = mt * 16 + ((r >> 1) << 3) + g;
                        numacc[mt * 2 + (r >> 1)] +=
                            acc[mt][nt][r] * Qb[kk * Q_LD + iloc] * ((r & 1) ? v2b : v2a);
                    }
            }
        }
        __syncthreads();  // all warps done reading this buffer before it's re-staged
    }

    // Reduce over quad lanes (tg), then across 8 warps via smem
#pragma unroll
    for (int s = 0; s < 8; ++s) {
        float v = numacc[s];
        v += __shfl_xor_sync(0xffffffffu, v, 1);
        v += __shfl_xor_sync(0xffffffffu, v, 2);
        if (tg == 0) {
            int iloc = (s >> 1) * 16 + (s & 1) * 8 + g;
            pp[w * NI + iloc] = v;
        }
    }
    __syncthreads();
    if (t < NI) {
        float tot = 0.f;
#pragma unroll
        for (int q = 0; q < 8; ++q) tot += pp[q * NI + t];
        int gi = i0 + t;
        if (d < C) g_num[gi * C + d] = tot;
        else       g_den[gi] = tot;
    }

    // Fused finalize: last CTA computes out = num / den
    __threadfence();
    __syncthreads();
    __shared__ unsigned s_last;
    if (t == 0) s_last = atomicAdd(&g_ctr, 1u);
    __syncthreads();
    if (s_last == gridDim.x * gridDim.y - 1) {
        for (int idx = t; idx < N * C; idx += THREADS)
            out[idx] = g_num[idx] / g_den[idx / C];
        if (t == 0) atomicExch(&g_ctr, 0u);   // reset for next graph replay
    }
}

// ---------------- launcher ----------------
extern "C" void kernel_launch(void* const* d_in, const int* in_sizes, int n_in,
                              void* d_out, int out_size) {
    const float* x  = (const float*)d_in[0];
    const float* ww = (const float*)d_in[1];
    if (n_in >= 2 && in_sizes[0] == 8 * C * C && in_sizes[1] == N * C) {
        const float* tmp = x; x = ww; ww = tmp;
    }
    float* out = (float*)d_out;

    cudaFuncSetAttribute(k_main, cudaFuncAttributeMaxDynamicSharedMemorySize, SMEM_BYTES);

    dim3 g1(W_COLS / 32, N / 32);
    k_gemm_w<<<g1, dim3(16, 16)>>>(x, ww);
    dim3 g2(N / 32, N / 32, 3);
    k_pqr<<<g2, dim3(16, 16)>>>();
    dim3 g3(C + 1, N / NI);
    k_main<<<g3, THREADS, SMEM_BYTES>>>(out);
}

// round 10
// speedup vs baseline: 1.3596x; 1.2942x over previous
#include <cuda_runtime.h>
#include <cstdint>

#define N 384
#define C 64
#define W_COLS 512
#define THREADS 256
#define NI 64             // i-rows per CTA
#define KCH 32            // k-chunk per stage
#define NCHUNK (N / KCH)  // 12
#define AS_LD 388         // fp32 words per B row (conflict-free fragment LDS)
#define Q_LD 68           // QT smem row stride (conflict-free fold)
#define NBUF 3

// ---------------- scratch ----------------
__device__ float g_W[N * W_COLS];        // x @ w_w^T  [384][512]
__device__ float g_P[N * N];             // exp(AB)  [i][j]
__device__ float g_QT[N * N];            // exp(CD) transposed: QT[k][i]
__device__ float g_RT[N * N];            // exp(EF) transposed, tf32-rounded: RT[k][j]
__device__ float g_num[N * C];
__device__ float g_den[N];

__device__ __forceinline__ float to_tf32(float x) {
    float r;
    asm("cvt.rna.tf32.f32 %0, %1;" : "=f"(r) : "f"(x));
    return r;
}
__device__ __forceinline__ void cp16(uint32_t dst, const void* src) {
    asm volatile("cp.async.cg.shared.global [%0], [%1], 16;" :: "r"(dst), "l"(src));
}

// ---------------- K1: W = x @ w_w^T, smem-tiled 32x32 (measured 8.5us) ----------------
__global__ void k_gemm_w(const float* __restrict__ x, const float* __restrict__ ww) {
    __shared__ float xs[32][67], ws[32][67];
    int o0 = blockIdx.x * 32, n0 = blockIdx.y * 32;
    int tx = threadIdx.x, ty = threadIdx.y;
    int t = ty * 16 + tx;
    for (int q = t; q < 32 * 64; q += 256) {
        int rr = q >> 6, cc = q & 63;
        xs[rr][cc] = x[(n0 + rr) * C + cc];
        ws[rr][cc] = ww[(o0 + rr) * C + cc];
    }
    __syncthreads();
    float s00 = 0.f, s01 = 0.f, s10 = 0.f, s11 = 0.f;
#pragma unroll
    for (int c = 0; c < 64; ++c) {
        float u0 = xs[2 * ty][c], u1 = xs[2 * ty + 1][c];
        float v0 = ws[2 * tx][c], v1 = ws[2 * tx + 1][c];
        s00 += u0 * v0; s01 += u0 * v1;
        s10 += u1 * v0; s11 += u1 * v1;
    }
    int n = n0 + 2 * ty, o = o0 + 2 * tx;
    g_W[n * W_COLS + o] = s00;       g_W[n * W_COLS + o + 1] = s01;
    g_W[(n + 1) * W_COLS + o] = s10; g_W[(n + 1) * W_COLS + o + 1] = s11;
}

// ---------------- K2: fused scores + exp (+transposes), 32x32 tiles ----------------
// No max-shift: scores are O(1) (w scaled 0.05); any per-matrix shift cancels in num/den.
__global__ void k_pqr() {
    __shared__ float us[32][67], vs[32][67];
    int z = blockIdx.z;
    int r0 = blockIdx.y * 32, c0 = blockIdx.x * 32;
    int tx = threadIdx.x, ty = threadIdx.y;
    int t = ty * 16 + tx;
    int up = (z == 0) ? 0 : (z == 1) ? 3 : 5;
    int vp = (z == 0) ? 1 : (z == 1) ? 2 : 4;
    for (int q = t; q < 32 * 64; q += 256) {
        int rr = q >> 6, cc = q & 63;
        us[rr][cc] = g_W[(r0 + rr) * W_COLS + up * C + cc];
        vs[rr][cc] = g_W[(c0 + rr) * W_COLS + vp * C + cc];
    }
    __syncthreads();
    float s00 = 0.f, s01 = 0.f, s10 = 0.f, s11 = 0.f;
#pragma unroll
    for (int c = 0; c < 64; ++c) {
        float u0 = us[2 * ty][c], u1 = us[2 * ty + 1][c];
        float v0 = vs[2 * tx][c], v1 = vs[2 * tx + 1][c];
        s00 += u0 * v0; s01 += u0 * v1;
        s10 += u1 * v0; s11 += u1 * v1;
    }
    s00 = __expf(s00 * 0.125f);
    s01 = __expf(s01 * 0.125f);
    s10 = __expf(s10 * 0.125f);
    s11 = __expf(s11 * 0.125f);
    int row = r0 + 2 * ty, col = c0 + 2 * tx;
    if (z == 0) {
        g_P[row * N + col] = s00;       g_P[row * N + col + 1] = s01;
        g_P[(row + 1) * N + col] = s10; g_P[(row + 1) * N + col + 1] = s11;
    } else if (z == 1) {
        g_QT[row * N + col] = s00;       g_QT[row * N + col + 1] = s01;
        g_QT[(row + 1) * N + col] = s10; g_QT[(row + 1) * N + col + 1] = s11;
    } else {
        g_RT[row * N + col] = to_tf32(s00);       g_RT[row * N + col + 1] = to_tf32(s01);
        g_RT[(row + 1) * N + col] = to_tf32(s10); g_RT[(row + 1) * N + col + 1] = to_tf32(s11);
    }
}

// ---------------- K3: tf32 HMMA main contraction (exact R6 config) ----------------
// grid = (65, 6): blockIdx.x = d (64 => denominator), blockIdx.y = i-tile (64 rows)
#define B_BYTES (KCH * AS_LD * 4)                  // 49664
#define Q_BYTES (KCH * Q_LD * 4)                   // 8704
#define OFF_B   0
#define OFF_QT  (NBUF * B_BYTES)                   // 148992
#define OFF_V1  (OFF_QT + NBUF * Q_BYTES)          // 175104
#define OFF_V2  (OFF_V1 + N * 4)
#define OFF_PP  (OFF_V2 + N * 4)
#define SMEM_BYTES (OFF_PP + 8 * NI * 4)           // 180224

__device__ __forceinline__ void mma_tf32(float* c, const uint32_t* a, const uint32_t* b) {
    asm("mma.sync.aligned.m16n8k8.row.col.f32.tf32.tf32.f32 "
        "{%0,%1,%2,%3}, {%4,%5,%6,%7}, {%8,%9}, {%0,%1,%2,%3};"
        : "+f"(c[0]), "+f"(c[1]), "+f"(c[2]), "+f"(c[3])
        : "r"(a[0]), "r"(a[1]), "r"(a[2]), "r"(a[3]), "r"(b[0]), "r"(b[1]));
}

__global__ __launch_bounds__(THREADS, 1) void k_main() {
    extern __shared__ char smc[];
    float* v1s = (float*)(smc + OFF_V1);
    float* v2s = (float*)(smc + OFF_V2);
    float* pp  = (float*)(smc + OFF_PP);

    int d = blockIdx.x;
    int i0 = blockIdx.y * NI;
    int t = threadIdx.x;
    int w = t >> 5, lane = t & 31;
    int g = lane >> 2, tg = lane & 3;
    int j0w = w * 48;

    uint32_t smb = (uint32_t)__cvta_generic_to_shared(smc);

    // Stage chunks 0 and 1
#pragma unroll
    for (int pc = 0; pc < 2; ++pc) {
        uint32_t bo = OFF_B + (uint32_t)pc * B_BYTES;
        uint32_t qo = OFF_QT + (uint32_t)pc * Q_BYTES;
        int k0 = pc * KCH;
        for (int q = t; q < KCH * (N / 4); q += THREADS) {
            int r = q / (N / 4), u = q - r * (N / 4);
            cp16(smb + bo + (uint32_t)(r * AS_LD + u * 4) * 4u, &g_RT[(k0 + r) * N + u * 4]);
        }
        for (int q = t; q < KCH * (NI / 4); q += THREADS) {
            int r = q / (NI / 4), u = q - r * (NI / 4);
            cp16(smb + qo + (uint32_t)(r * Q_LD + u * 4) * 4u, &g_QT[(k0 + r) * N + i0 + u * 4]);
        }
        asm volatile("cp.async.commit_group;" ::: "memory");
    }

    if (d < C) {
        for (int j = t; j < N; j += THREADS) {
            v1s[j] = g_W[j * W_COLS + 6 * C + d];
            v2s[j] = g_W[j * W_COLS + 7 * C + d];
        }
    } else {
        for (int j = t; j < N; j += THREADS) { v1s[j] = 1.f; v2s[j] = 1.f; }
    }
    __syncthreads();

    // Hoist A fragments into registers: chunk-invariant, built from g_P * v1
    uint32_t a[4][6][4];
#pragma unroll
    for (int mt = 0; mt < 4; ++mt)
#pragma unroll
        for (int js = 0; js < 6; ++js) {
            int i = i0 + mt * 16 + g;
            int j = j0w + js * 8 + tg;
            float v1a = v1s[j], v1b = v1s[j + 4];
            a[mt][js][0] = __float_as_uint(to_tf32(g_P[i * N + j] * v1a));
            a[mt][js][1] = __float_as_uint(to_tf32(g_P[(i + 8) * N + j] * v1a));
            a[mt][js][2] = __float_as_uint(to_tf32(g_P[i * N + j + 4] * v1b));
            a[mt][js][3] = __float_as_uint(to_tf32(g_P[(i + 8) * N + j + 4] * v1b));
        }

    float numacc[8];
#pragma unroll
    for (int s = 0; s < 8; ++s) numacc[s] = 0.f;

    for (int ch = 0; ch < NCHUNK; ++ch) {
        if (ch + 2 < NCHUNK) {
            uint32_t bo = OFF_B + (uint32_t)((ch + 2) % NBUF) * B_BYTES;
            uint32_t qo = OFF_QT + (uint32_t)((ch + 2) % NBUF) * Q_BYTES;
            int k0 = (ch + 2) * KCH;
            for (int q = t; q < KCH * (N / 4); q += THREADS) {
                int r = q / (N / 4), u = q - r * (N / 4);
                cp16(smb + bo + (uint32_t)(r * AS_LD + u * 4) * 4u, &g_RT[(k0 + r) * N + u * 4]);
            }
            for (int q = t; q < KCH * (NI / 4); q += THREADS) {
                int r = q / (NI / 4), u = q - r * (NI / 4);
                cp16(smb + qo + (uint32_t)(r * Q_LD + u * 4) * 4u, &g_QT[(k0 + r) * N + i0 + u * 4]);
            }
            asm volatile("cp.async.commit_group;" ::: "memory");
            asm volatile("cp.async.wait_group 2;" ::: "memory");
        } else if (ch + 2 == NCHUNK) {
            asm volatile("cp.async.wait_group 1;" ::: "memory");
        } else {
            asm volatile("cp.async.wait_group 0;" ::: "memory");
        }
        __syncthreads();

        const float* Bb = (const float*)(smc + OFF_B + (ch % NBUF) * B_BYTES);
        const float* Qb = (const float*)(smc + OFF_QT + (ch % NBUF) * Q_BYTES);

#pragma unroll
        for (int half = 0; half < 2; ++half) {
            float acc[4][2][4];
#pragma unroll
            for (int mt = 0; mt < 4; ++mt)
#pragma unroll
                for (int nt = 0; nt < 2; ++nt)
#pragma unroll
                    for (int r = 0; r < 4; ++r) acc[mt][nt][r] = 0.f;

#pragma unroll
            for (int js = 0; js < 6; ++js) {
                int j0 = j0w + js * 8;
                uint32_t b[2][2];
#pragma unroll
                for (int nt = 0; nt < 2; ++nt) {
                    const uint32_t* bp =
                        (const uint32_t*)(Bb + (half * 16 + nt * 8 + g) * AS_LD + j0 + tg);
                    b[nt][0] = bp[0];
                    b[nt][1] = bp[4];
                }
#pragma unroll
                for (int mt = 0; mt < 4; ++mt)
#pragma unroll
                    for (int nt = 0; nt < 2; ++nt)
                        mma_tf32(acc[mt][nt], a[mt][js], b[nt]);
            }

            // Fold: numacc += G * QT[k][i] * v2[k]
#pragma unroll
            for (int nt = 0; nt < 2; ++nt) {
                int kk0 = half * 16 + nt * 8 + 2 * tg;
                float v2a = v2s[ch * KCH + kk0];
                float v2b = v2s[ch * KCH + kk0 + 1];
#pragma unroll
                for (int mt = 0; mt < 4; ++mt)
#pragma unroll
                    for (int r = 0; r < 4; ++r) {
                        int kk = kk0 + (r & 1);
                        int iloc = mt * 16 + ((r >> 1) << 3) + g;
                        numacc[mt * 2 + (r >> 1)] +=
                            acc[mt][nt][r] * Qb[kk * Q_LD + iloc] * ((r & 1) ? v2b : v2a);
                    }
            }
        }
        __syncthreads();  // all warps done reading this buffer before it's re-staged
    }

    // Reduce over quad lanes (tg), then across 8 warps via smem
#pragma unroll
    for (int s = 0; s < 8; ++s) {
        float v = numacc[s];
        v += __shfl_xor_sync(0xffffffffu, v, 1);
        v += __shfl_xor_sync(0xffffffffu, v, 2);
        if (tg == 0) {
            int iloc = (s >> 1) * 16 + (s & 1) * 8 + g;
            pp[w * NI + iloc] = v;
        }
    }
    __syncthreads();
    if (t < NI) {
        float tot = 0.f;
#pragma unroll
        for (int q = 0; q < 8; ++q) tot += pp[q * NI + t];
        int gi = i0 + t;
        if (d < C) g_num[gi * C + d] = tot;
        else       g_den[gi] = tot;
    }
}

// ---------------- K4: out = num / den ----------------
__global__ void k_final(float* __restrict__ out) {
    int idx = blockIdx.x * blockDim.x + threadIdx.x;
    if (idx >= N * C) return;
    int i = idx / C;
    out[idx] = g_num[idx] / g_den[i];
}

// ---------------- launcher ----------------
extern "C" void kernel_launch(void* const* d_in, const int* in_sizes, int n_in,
                              void* d_out, int out_size) {
    const float* x  = (const float*)d_in[0];
    const float* ww = (const float*)d_in[1];
    if (n_in >= 2 && in_sizes[0] == 8 * C * C && in_sizes[1] == N * C) {
        const float* tmp = x; x = ww; ww = tmp;
    }
    float* out = (float*)d_out;

    cudaFuncSetAttribute(k_main, cudaFuncAttributeMaxDynamicSharedMemorySize, SMEM_BYTES);

    dim3 g1(W_COLS / 32, N / 32);
    k_gemm_w<<<g1, dim3(16, 16)>>>(x, ww);
    dim3 g2(N / 32, N / 32, 3);
    k_pqr<<<g2, dim3(16, 16)>>>();
    dim3 g3(C + 1, N / NI);
    k_main<<<g3, THREADS, SMEM_BYTES>>>();
    k_final<<<(N * C + THREADS - 1) / THREADS, THREADS>>>(out);
}